// round 2
// baseline (speedup 1.0000x reference)
#include <cuda_runtime.h>

// Problem constants (fixed shapes from reference setup_inputs)
#define BB 64
#define CC 256
#define TT 2048
#define N_PER_CH (BB * TT)          // 131072 samples per channel
#define CT (CC * TT)                // 524288
#define CT4 (CT / 4)                // 131072 float4 per [C,T] plane
#define TOTAL4 (BB * CT / 4)        // 8388608 float4 total
#define EPS 1e-4f
#define RED_SPLIT 4                 // batch-dim split for the reduce pass
#define B_PER_BLK (BB / RED_SPLIT)  // 16 batch rows per reduce block

// Device scratch (allocation-free rule: __device__ globals)
__device__ float g_psum[RED_SPLIT * CC];   // per-(split,channel) partial sums
__device__ float g_psq[RED_SPLIT * CC];
__device__ float g_A[CT];           // [C, T] layout: scale  = rs[c]*gamma[t,c]
__device__ float g_Boff[CT];        // [C, T] layout: offset = beta[t,c] - mean[c]*scale

// ---------------------------------------------------------------------------
// Kernel 1: per-channel partial sum / sumsq.
// Grid (CC, RED_SPLIT): block (c, q) sums 16 rows x[b][c][:], b in [16q,16q+16).
// 256 threads x 32 float4 each, fully unrolled for high MLP. One block-reduce
// tail per 128 KB of data. Partials written without atomics (deterministic,
// no zeroing kernel needed).
// ---------------------------------------------------------------------------
__global__ __launch_bounds__(256) void reduce_kernel(const float4* __restrict__ x) {
    const int c = blockIdx.x;
    const int q = blockIdx.y;
    const int tid = threadIdx.x;

    float s = 0.0f, sq = 0.0f;
#pragma unroll
    for (int bb = 0; bb < B_PER_BLK; bb++) {
        const int b = q * B_PER_BLK + bb;
        const float4* p = x + (size_t)(b * CC + c) * (TT / 4);
#pragma unroll
        for (int k = 0; k < 2; k++) {
            float4 v = __ldcs(&p[tid + k * 256]);   // streaming: don't pollute L2
            s  += (v.x + v.y) + (v.z + v.w);
            sq += (v.x * v.x + v.y * v.y) + (v.z * v.z + v.w * v.w);
        }
    }

    // warp reduce
#pragma unroll
    for (int off = 16; off > 0; off >>= 1) {
        s  += __shfl_down_sync(0xFFFFFFFFu, s,  off);
        sq += __shfl_down_sync(0xFFFFFFFFu, sq, off);
    }

    __shared__ float ws[8], wq[8];
    const int warp = tid >> 5;
    const int lane = tid & 31;
    if (lane == 0) { ws[warp] = s; wq[warp] = sq; }
    __syncthreads();

    if (warp == 0) {
        s  = (lane < 8) ? ws[lane] : 0.0f;
        sq = (lane < 8) ? wq[lane] : 0.0f;
#pragma unroll
        for (int off = 4; off > 0; off >>= 1) {
            s  += __shfl_down_sync(0xFFFFFFFFu, s,  off);
            sq += __shfl_down_sync(0xFFFFFFFFu, sq, off);
        }
        if (lane == 0) {
            g_psum[q * CC + c] = s;
            g_psq[q * CC + c]  = sq;
        }
    }
}

// ---------------------------------------------------------------------------
// Kernel 2: build fused affine A/B in [C, T] layout (transpose gamma/beta
// from [T, C] via 32x32 shared tile).
//   A[c][t] = rs[c] * gamma[t][c]
//   B[c][t] = beta[t][c] - mean[c] * A[c][t]
// Grid: (CC/32, TT/32), block (32, 8).
// ---------------------------------------------------------------------------
__global__ __launch_bounds__(256) void prep_kernel(const float* __restrict__ gamma,
                                                   const float* __restrict__ beta) {
    __shared__ float sg[32][33];
    __shared__ float sb[32][33];

    const int cBase = blockIdx.x * 32;
    const int tBase = blockIdx.y * 32;

    // load: rows = t, cols = c (coalesced over c)
#pragma unroll
    for (int r = 0; r < 4; r++) {
        const int tl = threadIdx.y + r * 8;
        const int t = tBase + tl;
        const int c = cBase + threadIdx.x;
        sg[tl][threadIdx.x] = gamma[t * CC + c];
        sb[tl][threadIdx.x] = beta[t * CC + c];
    }
    __syncthreads();

    // write: rows = c, cols = t (coalesced over t)
#pragma unroll
    for (int r = 0; r < 4; r++) {
        const int cl = threadIdx.y + r * 8;
        const int c = cBase + cl;
        const int t = tBase + threadIdx.x;

        float s = 0.0f, sq = 0.0f;
#pragma unroll
        for (int qq = 0; qq < RED_SPLIT; qq++) {
            s  += g_psum[qq * CC + c];
            sq += g_psq[qq * CC + c];
        }
        const float inv_n = 1.0f / (float)N_PER_CH;
        const float mean = s * inv_n;
        const float var = fmaxf(sq * inv_n - mean * mean, 0.0f);
        const float rs = rsqrtf(var + EPS);

        const float gv = sg[threadIdx.x][cl];
        const float bv = sb[threadIdx.x][cl];
        const float a = gv * rs;
        g_A[c * TT + t] = a;
        g_Boff[c * TT + t] = bv - mean * a;
    }
}

// ---------------------------------------------------------------------------
// Kernel 3: elementwise out[i] = x[i] * A[j] + B[j], j = i mod (C*T).
// 4 float4 per thread, front-batched loads for MLP. x/out streaming so A/B
// (4 MiB) stay L2-resident across the B=64 reuse.
// ---------------------------------------------------------------------------
__global__ __launch_bounds__(256) void norm_kernel(const float4* __restrict__ x,
                                                   float4* __restrict__ out) {
    const unsigned base = blockIdx.x * 1024u + threadIdx.x;   // 4 f4 per thread

    const float4* __restrict__ A4 = (const float4*)g_A;
    const float4* __restrict__ B4 = (const float4*)g_Boff;

    float4 v[4], a[4], b[4];
#pragma unroll
    for (int k = 0; k < 4; k++) {
        const unsigned i = base + k * 256u;
        const unsigned j = i & (CT4 - 1u);
        v[k] = __ldcs(&x[i]);
        a[k] = __ldg(&A4[j]);
        b[k] = __ldg(&B4[j]);
    }

#pragma unroll
    for (int k = 0; k < 4; k++) {
        float4 o;
        o.x = fmaf(v[k].x, a[k].x, b[k].x);
        o.y = fmaf(v[k].y, a[k].y, b[k].y);
        o.z = fmaf(v[k].z, a[k].z, b[k].z);
        o.w = fmaf(v[k].w, a[k].w, b[k].w);
        __stcs(&out[base + k * 256u], o);
    }
}

// ---------------------------------------------------------------------------
extern "C" void kernel_launch(void* const* d_in, const int* in_sizes, int n_in,
                              void* d_out, int out_size) {
    const float* x = (const float*)d_in[0];
    const float* gamma = (const float*)d_in[1];
    const float* beta = (const float*)d_in[2];
    float* out = (float*)d_out;

    reduce_kernel<<<dim3(CC, RED_SPLIT), 256>>>((const float4*)x);
    {
        dim3 grid(CC / 32, TT / 32);
        dim3 block(32, 8);
        prep_kernel<<<grid, block>>>(gamma, beta);
    }
    norm_kernel<<<TOTAL4 / 1024, 256>>>((const float4*)x, (float4*)out);
}

// round 3
// speedup vs baseline: 1.1116x; 1.1116x over previous
#include <cuda_runtime.h>

// Problem constants (fixed shapes from reference setup_inputs)
#define BB 64
#define CC 256
#define TT 2048
#define N_PER_CH (BB * TT)          // 131072 samples per channel
#define CT (CC * TT)                // 524288
#define CT4 (CT / 4)                // 131072 float4 per [C,T] plane
#define TOTAL4 (BB * CT / 4)        // 8388608 float4 total
#define EPS 1e-4f
#define RED_SPLIT 8                 // batch-dim split for the reduce pass
#define B_PER_BLK (BB / RED_SPLIT)  // 8 batch rows per reduce block

// Device scratch (allocation-free rule: __device__ globals)
__device__ float g_psum[RED_SPLIT * CC];   // per-(split,channel) partial sums
__device__ float g_psq[RED_SPLIT * CC];
__device__ float g_A[CT];           // [C, T] layout: scale  = rs[c]*gamma[t,c]
__device__ float g_Boff[CT];        // [C, T] layout: offset = beta[t,c] - mean[c]*scale

// ---------------------------------------------------------------------------
// Kernel 1: per-channel partial sum / sumsq.
// Grid (CC, RED_SPLIT): block (c, q) sums 8 rows x[b][c][:], b in [8q, 8q+8).
// 256 threads x 16 float4 each. One block-reduce tail per 64 KB of data.
// Partials written without atomics (deterministic, no zeroing kernel needed).
// ---------------------------------------------------------------------------
__global__ __launch_bounds__(256) void reduce_kernel(const float4* __restrict__ x) {
    const int c = blockIdx.x;
    const int q = blockIdx.y;
    const int tid = threadIdx.x;

    float s = 0.0f, sq = 0.0f;
#pragma unroll
    for (int bb = 0; bb < B_PER_BLK; bb++) {
        const int b = q * B_PER_BLK + bb;
        const float4* p = x + (size_t)(b * CC + c) * (TT / 4);
#pragma unroll
        for (int k = 0; k < 2; k++) {
            float4 v = __ldcs(&p[tid + k * 256]);   // streaming: don't pollute L2
            s  += (v.x + v.y) + (v.z + v.w);
            sq += (v.x * v.x + v.y * v.y) + (v.z * v.z + v.w * v.w);
        }
    }

    // warp reduce
#pragma unroll
    for (int off = 16; off > 0; off >>= 1) {
        s  += __shfl_down_sync(0xFFFFFFFFu, s,  off);
        sq += __shfl_down_sync(0xFFFFFFFFu, sq, off);
    }

    __shared__ float ws[8], wq[8];
    const int warp = tid >> 5;
    const int lane = tid & 31;
    if (lane == 0) { ws[warp] = s; wq[warp] = sq; }
    __syncthreads();

    if (warp == 0) {
        s  = (lane < 8) ? ws[lane] : 0.0f;
        sq = (lane < 8) ? wq[lane] : 0.0f;
#pragma unroll
        for (int off = 4; off > 0; off >>= 1) {
            s  += __shfl_down_sync(0xFFFFFFFFu, s,  off);
            sq += __shfl_down_sync(0xFFFFFFFFu, sq, off);
        }
        if (lane == 0) {
            g_psum[q * CC + c] = s;
            g_psq[q * CC + c]  = sq;
        }
    }
}

// ---------------------------------------------------------------------------
// Kernel 2: build fused affine A/B in [C, T] layout (transpose gamma/beta
// from [T, C] via 32x32 shared tile).
//   A[c][t] = rs[c] * gamma[t][c]
//   B[c][t] = beta[t][c] - mean[c] * A[c][t]
// Grid: (CC/32, TT/32), block (32, 8).
// ---------------------------------------------------------------------------
__global__ __launch_bounds__(256) void prep_kernel(const float* __restrict__ gamma,
                                                   const float* __restrict__ beta) {
    __shared__ float sg[32][33];
    __shared__ float sb[32][33];

    const int cBase = blockIdx.x * 32;
    const int tBase = blockIdx.y * 32;

    // load: rows = t, cols = c (coalesced over c)
#pragma unroll
    for (int r = 0; r < 4; r++) {
        const int tl = threadIdx.y + r * 8;
        const int t = tBase + tl;
        const int c = cBase + threadIdx.x;
        sg[tl][threadIdx.x] = gamma[t * CC + c];
        sb[tl][threadIdx.x] = beta[t * CC + c];
    }
    __syncthreads();

    // write: rows = c, cols = t (coalesced over t)
#pragma unroll
    for (int r = 0; r < 4; r++) {
        const int cl = threadIdx.y + r * 8;
        const int c = cBase + cl;
        const int t = tBase + threadIdx.x;

        float s = 0.0f, sq = 0.0f;
#pragma unroll
        for (int qq = 0; qq < RED_SPLIT; qq++) {
            s  += g_psum[qq * CC + c];
            sq += g_psq[qq * CC + c];
        }
        const float inv_n = 1.0f / (float)N_PER_CH;
        const float mean = s * inv_n;
        const float var = fmaxf(sq * inv_n - mean * mean, 0.0f);
        const float rs = rsqrtf(var + EPS);

        const float gv = sg[threadIdx.x][cl];
        const float bv = sb[threadIdx.x][cl];
        const float a = gv * rs;
        g_A[c * TT + t] = a;
        g_Boff[c * TT + t] = bv - mean * a;
    }
}

// ---------------------------------------------------------------------------
// Kernel 3: elementwise out[i] = x[i] * A[j] + B[j], j = i mod (C*T).
// Round-1 proven form: 1 float4/thread, low MLP_p1 -> stays at the multi-CTA
// spread floor. x/out streaming so A/B (4 MiB) stay L2-resident across the
// B=64 reuse.
// ---------------------------------------------------------------------------
__global__ __launch_bounds__(256) void norm_kernel(const float4* __restrict__ x,
                                                   float4* __restrict__ out) {
    const unsigned i = blockIdx.x * 256u + threadIdx.x;   // < TOTAL4 = 2^23
    const unsigned j = i & (CT4 - 1u);

    const float4* __restrict__ A4 = (const float4*)g_A;
    const float4* __restrict__ B4 = (const float4*)g_Boff;

    float4 v = __ldcs(&x[i]);
    float4 a = __ldg(&A4[j]);
    float4 b = __ldg(&B4[j]);

    float4 o;
    o.x = fmaf(v.x, a.x, b.x);
    o.y = fmaf(v.y, a.y, b.y);
    o.z = fmaf(v.z, a.z, b.z);
    o.w = fmaf(v.w, a.w, b.w);
    __stcs(&out[i], o);
}

// ---------------------------------------------------------------------------
extern "C" void kernel_launch(void* const* d_in, const int* in_sizes, int n_in,
                              void* d_out, int out_size) {
    const float* x = (const float*)d_in[0];
    const float* gamma = (const float*)d_in[1];
    const float* beta = (const float*)d_in[2];
    float* out = (float*)d_out;

    reduce_kernel<<<dim3(CC, RED_SPLIT), 256>>>((const float4*)x);
    {
        dim3 grid(CC / 32, TT / 32);
        dim3 block(32, 8);
        prep_kernel<<<grid, block>>>(gamma, beta);
    }
    norm_kernel<<<TOTAL4 / 256, 256>>>((const float4*)x, (float4*)out);
}

// round 4
// speedup vs baseline: 1.1614x; 1.0448x over previous
#include <cuda_runtime.h>

// Problem constants (fixed shapes from reference setup_inputs)
#define BB 64
#define CC 256
#define TT 2048
#define N_PER_CH (BB * TT)          // 131072 samples per channel
#define CT (CC * TT)                // 524288
#define CT4 (CT / 4)                // 131072 float4 per [C,T] plane
#define TOTAL4 (BB * CT / 4)        // 8388608 float4 total
#define EPS 1e-4f
#define RED_SPLIT 8                 // batch-dim split for the reduce pass
#define B_PER_BLK (BB / RED_SPLIT)  // 8 batch rows per reduce block
#define BSPLIT 16                   // batch-dim split for the norm pass
#define B_PER_NORM (BB / BSPLIT)    // 4 images per norm block

// Device scratch (allocation-free rule: __device__ globals)
__device__ float g_psum[RED_SPLIT * CC];   // per-(split,channel) partial sums
__device__ float g_psq[RED_SPLIT * CC];
__device__ float g_A[CT];           // [C, T] layout: scale  = rs[c]*gamma[t,c]
__device__ float g_Boff[CT];        // [C, T] layout: offset = beta[t,c] - mean[c]*scale

// ---------------------------------------------------------------------------
// Kernel 1: per-channel partial sum / sumsq.
// Grid (CC, RED_SPLIT). DEFAULT cache policy on purpose: x (134 MB) nearly
// fits in L2 (~126 MB); leaving it resident lets the norm pass serve most of
// its x-reads from L2, halving that pass's DRAM read traffic.
// ---------------------------------------------------------------------------
__global__ __launch_bounds__(256) void reduce_kernel(const float4* __restrict__ x) {
    const int c = blockIdx.x;
    const int q = blockIdx.y;
    const int tid = threadIdx.x;

    float s = 0.0f, sq = 0.0f;
#pragma unroll
    for (int bb = 0; bb < B_PER_BLK; bb++) {
        const int b = q * B_PER_BLK + bb;
        const float4* p = x + (size_t)(b * CC + c) * (TT / 4);
#pragma unroll
        for (int k = 0; k < 2; k++) {
            float4 v = p[tid + k * 256];            // keep resident in L2
            s  += (v.x + v.y) + (v.z + v.w);
            sq += (v.x * v.x + v.y * v.y) + (v.z * v.z + v.w * v.w);
        }
    }

    // warp reduce
#pragma unroll
    for (int off = 16; off > 0; off >>= 1) {
        s  += __shfl_down_sync(0xFFFFFFFFu, s,  off);
        sq += __shfl_down_sync(0xFFFFFFFFu, sq, off);
    }

    __shared__ float ws[8], wq[8];
    const int warp = tid >> 5;
    const int lane = tid & 31;
    if (lane == 0) { ws[warp] = s; wq[warp] = sq; }
    __syncthreads();

    if (warp == 0) {
        s  = (lane < 8) ? ws[lane] : 0.0f;
        sq = (lane < 8) ? wq[lane] : 0.0f;
#pragma unroll
        for (int off = 4; off > 0; off >>= 1) {
            s  += __shfl_down_sync(0xFFFFFFFFu, s,  off);
            sq += __shfl_down_sync(0xFFFFFFFFu, sq, off);
        }
        if (lane == 0) {
            g_psum[q * CC + c] = s;
            g_psq[q * CC + c]  = sq;
        }
    }
}

// ---------------------------------------------------------------------------
// Kernel 2: build fused affine A/B in [C, T] layout (transpose gamma/beta
// from [T, C] via 32x32 shared tile).
//   A[c][t] = rs[c] * gamma[t][c]
//   B[c][t] = beta[t][c] - mean[c] * A[c][t]
// Grid: (CC/32, TT/32), block (32, 8).
// ---------------------------------------------------------------------------
__global__ __launch_bounds__(256) void prep_kernel(const float* __restrict__ gamma,
                                                   const float* __restrict__ beta) {
    __shared__ float sg[32][33];
    __shared__ float sb[32][33];

    const int cBase = blockIdx.x * 32;
    const int tBase = blockIdx.y * 32;

    // load: rows = t, cols = c (coalesced over c)
#pragma unroll
    for (int r = 0; r < 4; r++) {
        const int tl = threadIdx.y + r * 8;
        const int t = tBase + tl;
        const int c = cBase + threadIdx.x;
        sg[tl][threadIdx.x] = gamma[t * CC + c];
        sb[tl][threadIdx.x] = beta[t * CC + c];
    }
    __syncthreads();

    // write: rows = c, cols = t (coalesced over t)
#pragma unroll
    for (int r = 0; r < 4; r++) {
        const int cl = threadIdx.y + r * 8;
        const int c = cBase + cl;
        const int t = tBase + threadIdx.x;

        float s = 0.0f, sq = 0.0f;
#pragma unroll
        for (int qq = 0; qq < RED_SPLIT; qq++) {
            s  += g_psum[qq * CC + c];
            sq += g_psq[qq * CC + c];
        }
        const float inv_n = 1.0f / (float)N_PER_CH;
        const float mean = s * inv_n;
        const float var = fmaxf(sq * inv_n - mean * mean, 0.0f);
        const float rs = rsqrtf(var + EPS);

        const float gv = sg[threadIdx.x][cl];
        const float bv = sb[threadIdx.x][cl];
        const float a = gv * rs;
        g_A[c * TT + t] = a;
        g_Boff[c * TT + t] = bv - mean * a;
    }
}

// ---------------------------------------------------------------------------
// Kernel 3: j-blocked normalize. Each block owns a 256-float4 segment of the
// A/B plane, loads it ONCE into registers, then applies it to B_PER_NORM
// batch images (4x cut in A/B L2 traffic, MLP_p1 ~ 4 to stay at the
// multi-CTA spread floor). x reads: __ldcs (last use, evict-first — most hit
// L2 thanks to the resident copy from pass 1). out writes: __stcs so they
// don't displace the resident x.
// Grid: (CT4/256, BSPLIT).
// ---------------------------------------------------------------------------
__global__ __launch_bounds__(256) void norm_kernel(const float4* __restrict__ x,
                                                   float4* __restrict__ out) {
    const unsigned j = blockIdx.x * 256u + threadIdx.x;   // < CT4
    const unsigned b0 = blockIdx.y * B_PER_NORM;

    const float4* __restrict__ A4 = (const float4*)g_A;
    const float4* __restrict__ B4 = (const float4*)g_Boff;

    const float4 a  = __ldg(&A4[j]);
    const float4 bo = __ldg(&B4[j]);

#pragma unroll
    for (int bb = 0; bb < B_PER_NORM; bb++) {
        const unsigned i = (b0 + bb) * (unsigned)CT4 + j;
        const float4 v = __ldcs(&x[i]);
        float4 o;
        o.x = fmaf(v.x, a.x, bo.x);
        o.y = fmaf(v.y, a.y, bo.y);
        o.z = fmaf(v.z, a.z, bo.z);
        o.w = fmaf(v.w, a.w, bo.w);
        __stcs(&out[i], o);
    }
}

// ---------------------------------------------------------------------------
extern "C" void kernel_launch(void* const* d_in, const int* in_sizes, int n_in,
                              void* d_out, int out_size) {
    const float* x = (const float*)d_in[0];
    const float* gamma = (const float*)d_in[1];
    const float* beta = (const float*)d_in[2];
    float* out = (float*)d_out;

    reduce_kernel<<<dim3(CC, RED_SPLIT), 256>>>((const float4*)x);
    {
        dim3 grid(CC / 32, TT / 32);
        dim3 block(32, 8);
        prep_kernel<<<grid, block>>>(gamma, beta);
    }
    norm_kernel<<<dim3(CT4 / 256, BSPLIT), 256>>>((const float4*)x, (float4*)out);
}